// round 4
// baseline (speedup 1.0000x reference)
#include <cuda_runtime.h>

// Cosine similarity per row: a,b [16,4096,256] f32 -> out [16,4096] f32.
// out[r] = dot(a_r,b_r) * rsqrt(max(|a_r|^2,EPS)) * rsqrt(max(|b_r|^2,EPS))
//
// One warp per row. Row = 256 floats = 64 float4. Lane i loads float4 i and
// i+32 from both a and b (4x LDG.128/lane, coalesced), then a 5-step shfl
// butterfly reduces (dot, sa, sb) simultaneously.

#define EPSV 1e-12f

__global__ __launch_bounds__(256, 8)
void cosine_rows_kernel(const float4* __restrict__ a4,
                        const float4* __restrict__ b4,
                        float* __restrict__ out,
                        int n_rows)
{
    const int warp_in_block = threadIdx.x >> 5;
    const int lane = threadIdx.x & 31;
    const int row = blockIdx.x * 8 + warp_in_block;   // 8 warps/block
    if (row >= n_rows) return;

    // Row base in float4 units: 256 floats = 64 float4 per row.
    const long base = (long)row * 64;

    // Front-batched loads: MLP=4 per lane.
    float4 av0 = __ldg(a4 + base + lane);
    float4 av1 = __ldg(a4 + base + lane + 32);
    float4 bv0 = __ldg(b4 + base + lane);
    float4 bv1 = __ldg(b4 + base + lane + 32);

    float dot = av0.x * bv0.x + av0.y * bv0.y + av0.z * bv0.z + av0.w * bv0.w
              + av1.x * bv1.x + av1.y * bv1.y + av1.z * bv1.z + av1.w * bv1.w;
    float sa  = av0.x * av0.x + av0.y * av0.y + av0.z * av0.z + av0.w * av0.w
              + av1.x * av1.x + av1.y * av1.y + av1.z * av1.z + av1.w * av1.w;
    float sb  = bv0.x * bv0.x + bv0.y * bv0.y + bv0.z * bv0.z + bv0.w * bv0.w
              + bv1.x * bv1.x + bv1.y * bv1.y + bv1.z * bv1.z + bv1.w * bv1.w;

    #pragma unroll
    for (int off = 16; off > 0; off >>= 1) {
        dot += __shfl_xor_sync(0xFFFFFFFFu, dot, off);
        sa  += __shfl_xor_sync(0xFFFFFFFFu, sa,  off);
        sb  += __shfl_xor_sync(0xFFFFFFFFu, sb,  off);
    }

    if (lane == 0) {
        float inv = rsqrtf(fmaxf(sa, EPSV)) * rsqrtf(fmaxf(sb, EPSV));
        out[row] = dot * inv;
    }
}

extern "C" void kernel_launch(void* const* d_in, const int* in_sizes, int n_in,
                              void* d_out, int out_size)
{
    const float4* a = (const float4*)d_in[0];
    const float4* b = (const float4*)d_in[1];
    float* out = (float*)d_out;

    const int n_rows = out_size;             // 16*4096 = 65536 rows
    const int blocks = (n_rows + 7) / 8;     // 8 warps (rows) per block

    cosine_rows_kernel<<<blocks, 256>>>(a, b, out, n_rows);
}